// round 1
// baseline (speedup 1.0000x reference)
#include <cuda_runtime.h>
#include <stdint.h>
#include <math.h>

// Problem constants: B=8, N=16, S=118, A=10, D=128, DK=64, H=2, FO=1
//
// Restructured math:
//   oa=[states|actions], op=[states|policies]          [B,16,128]
//   k,q = oa @ W{k,q}[h]^T                              [B,H,16,64]
//   weight[b,h,i,j] = softmax_j(q[j].k[i]/8)
//   av_oa = tanh(oa@Wv^T), av_op = tanh(op@Wv^T)        [B,H,16,64]
//   weighted[b,h,i,j,e] = (base[i,e] + w[i,j]*(av_op-av_oa)[j,e])/16 + nm
//       base = weight @ av_oa
//   nm = mean_k of jax.random.uniform(key(42), (8,2,16,16,16,64)) noise
//        (threefry2x32 PARTITIONABLE variant: bits = o0^o1 of
//         threefry((0,42),(0, linear_index)); flip to split-counts variant
//         if rel_err comes back ~1e-2)
//   value = leakyrelu(f @ W1^T) @ W2^T, f = concat_h weighted
//
// Output layout assumed: value (2048 f32) then weight (4096 f32).

// ---------------- scratch ----------------
__device__ float g_k[16 * 16 * 64];
__device__ float g_q[16 * 16 * 64];
__device__ float g_aoa[16 * 16 * 64];
__device__ float g_aop[16 * 16 * 64];
__device__ float g_nm[16 * 16 * 16 * 64];  // [(bh*16+i)*16+j]*64+e

// ---------------- threefry2x32, key = (0, 42) ----------------
__device__ __forceinline__ void tf2x32(uint32_t x0, uint32_t x1,
                                       uint32_t& o0, uint32_t& o1) {
  const uint32_t k0 = 0u, k1 = 42u;
  const uint32_t k2 = k0 ^ k1 ^ 0x1BD11BDAu;
  x0 += k0; x1 += k1;
#define TF_RND(r) { x0 += x1; x1 = __funnelshift_l(x1, x1, (r)); x1 ^= x0; }
  TF_RND(13) TF_RND(15) TF_RND(26) TF_RND(6)
  x0 += k1; x1 += k2 + 1u;
  TF_RND(17) TF_RND(29) TF_RND(16) TF_RND(24)
  x0 += k2; x1 += k0 + 2u;
  TF_RND(13) TF_RND(15) TF_RND(26) TF_RND(6)
  x0 += k0; x1 += k1 + 3u;
  TF_RND(17) TF_RND(29) TF_RND(16) TF_RND(24)
  x0 += k1; x1 += k2 + 4u;
  TF_RND(13) TF_RND(15) TF_RND(26) TF_RND(6)
  x0 += k2; x1 += k0 + 5u;
#undef TF_RND
  o0 = x0; o1 = x1;
}

// ---------------- K1: projections. grid = 64 = (bh<<2)|tensor ----------------
// tensor: 0=k(oa,Wk) 1=q(oa,Wq) 2=av_oa(oa,Wv,tanh) 3=av_op(op,Wv,tanh)
__global__ void __launch_bounds__(256) k_proj(
    const float* __restrict__ states, const float* __restrict__ policies,
    const float* __restrict__ actions, const float* __restrict__ Wk,
    const float* __restrict__ Wq, const float* __restrict__ Wv) {
  __shared__ float src_s[16 * 129];
  __shared__ float w_s[64 * 129];
  const int bx = blockIdx.x;
  const int bh = bx >> 2, tensor = bx & 3;
  const int b = bh >> 1, h = bh & 1;
  const int t = threadIdx.x;
  const bool use_op = (tensor == 3);

  for (int idx = t; idx < 2048; idx += 256) {
    int n = idx >> 7, d = idx & 127;
    float v;
    if (d < 118) v = states[(b * 16 + n) * 118 + d];
    else v = use_op ? policies[(b * 16 + n) * 10 + d - 118]
                    : actions[(b * 16 + n) * 10 + d - 118];
    src_s[n * 129 + d] = v;
  }
  const float* W = (tensor == 0) ? Wk : (tensor == 1) ? Wq : Wv;
  for (int idx = t; idx < 8192; idx += 256)
    w_s[(idx >> 7) * 129 + (idx & 127)] = W[h * 8192 + idx];
  __syncthreads();

  const int el = t & 31;          // e in {el, el+32}  (conflict-free)
  const int n0 = (t >> 5) * 2;    // n in {n0, n0+1}   (warp-uniform)
  float a00 = 0.f, a01 = 0.f, a10 = 0.f, a11 = 0.f;
#pragma unroll 8
  for (int d = 0; d < 128; d++) {
    float w0 = w_s[el * 129 + d];
    float w1 = w_s[(el + 32) * 129 + d];
    float x0 = src_s[n0 * 129 + d];
    float x1 = src_s[(n0 + 1) * 129 + d];
    a00 = fmaf(x0, w0, a00); a01 = fmaf(x0, w1, a01);
    a10 = fmaf(x1, w0, a10); a11 = fmaf(x1, w1, a11);
  }
  if (tensor >= 2) {
    a00 = tanhf(a00); a01 = tanhf(a01); a10 = tanhf(a10); a11 = tanhf(a11);
  }
  float* outp = (tensor == 0) ? g_k : (tensor == 1) ? g_q
               : (tensor == 2) ? g_aoa : g_aop;
  const int base = bh * 1024;
  outp[base + n0 * 64 + el]            = a00;
  outp[base + n0 * 64 + el + 32]       = a01;
  outp[base + (n0 + 1) * 64 + el]      = a10;
  outp[base + (n0 + 1) * 64 + el + 32] = a11;
}

// ---------------- K2: noise means. grid = 1024x256 ----------------
// thread tid -> (bh,i,j,e); loops the 16 'k' samples; writes mean noise.
__global__ void __launch_bounds__(256) k_noise() {
  const unsigned tid = blockIdx.x * 256u + threadIdx.x;  // < 262144
  const uint32_t cbase = ((tid >> 6) << 10) | (tid & 63u);  // base3*1024 + e
  float s = 0.f;
#pragma unroll
  for (int k = 0; k < 16; k++) {
    uint32_t o0, o1;
    tf2x32(0u, cbase + (uint32_t)(k * 64), o0, o1);
    uint32_t bits = o0 ^ o1;
    s += __uint_as_float((bits >> 9) | 0x3f800000u);  // u + 1
  }
  // mean over k of (u-0.5)*0.1, with s = sum(u+1)
  g_nm[tid] = 0.1f * (s * 0.0625f - 1.5f);
}

// ---------------- K3: softmax + assemble + MLP. grid = 128 = b*16+i ----------
__global__ void __launch_bounds__(256) k_final(
    const float* __restrict__ W1, const float* __restrict__ W2,
    float* __restrict__ value_out, float* __restrict__ weight_out) {
  extern __shared__ float sm[];
  float* W1s   = sm;              // 64*129 = 8256
  float* fsh   = W1s + 8256;      // 16*129 = 2064
  float* qs    = fsh + 2064;      // 2*16*65 = 2080
  float* aoas  = qs + 2080;       // 2080
  float* aops  = aoas + 2080;     // 2080
  float* ki    = aops + 2080;     // 128
  float* W2s   = ki + 128;        // 64
  float* sc    = W2s + 64;        // 32
  float* wr    = sc + 32;         // 32
  float* bases = wr + 32;         // 128
  const int bi = blockIdx.x;
  const int b = bi >> 4, i = bi & 15;
  const int t = threadIdx.x;

  for (int idx = t; idx < 8192; idx += 256)
    W1s[(idx >> 7) * 129 + (idx & 127)] = W1[idx];
  if (t < 64) W2s[t] = W2[t];
  for (int idx = t; idx < 2048; idx += 256) {
    int h = idx >> 10, rest = idx & 1023;
    int j = rest >> 6, e = rest & 63;
    int g = (b * 2 + h) * 1024 + j * 64 + e;
    int s = h * 1040 + j * 65 + e;
    qs[s]   = g_q[g];
    aoas[s] = g_aoa[g];
    aops[s] = g_aop[g];
  }
  if (t < 128) {
    int h = t >> 6, e = t & 63;
    ki[t] = g_k[(b * 2 + h) * 1024 + i * 64 + e];
  }
  __syncthreads();

  // scores[h][j] = q[h,j] . k[h,i] / 8
  if (t < 32) {
    int h = t >> 4, j = t & 15;
    float acc = 0.f;
#pragma unroll
    for (int e = 0; e < 64; e++)
      acc = fmaf(qs[h * 1040 + j * 65 + e], ki[h * 64 + e], acc);
    sc[h * 16 + j] = acc * 0.125f;
  }
  __syncthreads();

  // softmax rows (one thread per head) + emit weight output
  if (t < 2) {
    int h = t;
    float m = -3.4e38f;
#pragma unroll
    for (int j = 0; j < 16; j++) m = fmaxf(m, sc[h * 16 + j]);
    float ex[16]; float ssum = 0.f;
#pragma unroll
    for (int j = 0; j < 16; j++) { ex[j] = expf(sc[h * 16 + j] - m); ssum += ex[j]; }
    float inv = 1.f / ssum;
#pragma unroll
    for (int j = 0; j < 16; j++) {
      float w = ex[j] * inv;
      wr[h * 16 + j] = w;
      if (weight_out) weight_out[((b * 2 + h) * 16 + i) * 16 + j] = w;
    }
  }
  __syncthreads();

  // base[h,e] = (1/16) sum_k w[h,k] * av_oa[h,k,e]
  if (t < 128) {
    int h = t >> 6, e = t & 63;
    float acc = 0.f;
#pragma unroll
    for (int k = 0; k < 16; k++)
      acc = fmaf(wr[h * 16 + k], aoas[h * 1040 + k * 65 + e], acc);
    bases[t] = acc * 0.0625f;
  }
  __syncthreads();

  // f[j][d], d = h*64+e
  for (int idx = t; idx < 2048; idx += 256) {
    int j = idx >> 7, d = idx & 127;
    int h = d >> 6, e = d & 63;
    int s = h * 1040 + j * 65 + e;
    float df = (aops[s] - aoas[s]) * 0.0625f;
    float nm = g_nm[(((b * 2 + h) * 16 + i) * 16 + j) * 64 + e];
    fsh[j * 129 + d] = fmaf(wr[h * 16 + j], df, bases[h * 64 + e]) + nm;
  }
  __syncthreads();

  // v[j,c] = lrelu(f[j] . W1[c]);  value[j] = sum_c v[j,c]*W2[c]
  const int lane = t & 31, jp = t >> 5;
  const int j0 = jp * 2, j1 = j0 + 1;
  const int c0 = lane, c1 = lane + 32;
  float a00 = 0.f, a01 = 0.f, a10 = 0.f, a11 = 0.f;
#pragma unroll 8
  for (int d = 0; d < 128; d++) {
    float f0 = fsh[j0 * 129 + d], f1 = fsh[j1 * 129 + d];
    float w0 = W1s[c0 * 129 + d], w1 = W1s[c1 * 129 + d];
    a00 = fmaf(f0, w0, a00); a01 = fmaf(f0, w1, a01);
    a10 = fmaf(f1, w0, a10); a11 = fmaf(f1, w1, a11);
  }
  a00 = a00 > 0.f ? a00 : 0.01f * a00;
  a01 = a01 > 0.f ? a01 : 0.01f * a01;
  a10 = a10 > 0.f ? a10 : 0.01f * a10;
  a11 = a11 > 0.f ? a11 : 0.01f * a11;
  float s0 = a00 * W2s[c0] + a01 * W2s[c1];
  float s1 = a10 * W2s[c0] + a11 * W2s[c1];
#pragma unroll
  for (int o = 16; o; o >>= 1) {
    s0 += __shfl_xor_sync(0xffffffffu, s0, o);
    s1 += __shfl_xor_sync(0xffffffffu, s1, o);
  }
  if (lane == 0 && value_out) {
    value_out[bi * 16 + j0] = s0;
    value_out[bi * 16 + j1] = s1;
  }
}

// ---------------- launch ----------------
extern "C" void kernel_launch(void* const* d_in, const int* in_sizes, int n_in,
                              void* d_out, int out_size) {
  const float* states   = (const float*)d_in[0];
  const float* policies = (const float*)d_in[1];
  const float* actions  = (const float*)d_in[2];
  const float* Wk = (const float*)d_in[3];
  const float* Wq = (const float*)d_in[4];
  const float* Wv = (const float*)d_in[5];
  const float* W1 = (const float*)d_in[6];
  const float* W2 = (const float*)d_in[7];

  float* out = (float*)d_out;
  float* value_out = out;
  float* weight_out = nullptr;
  if (out_size >= 6144) {
    weight_out = out + 2048;                 // (value, weight) concatenated
  } else if (out_size == 4096) {
    weight_out = out; value_out = nullptr;   // weight only
  }

  // k_final uses 67776 B dynamic smem (> 48KB static limit)
  cudaFuncSetAttribute(k_final, cudaFuncAttributeMaxDynamicSharedMemorySize,
                       16944 * (int)sizeof(float));

  k_proj<<<64, 256>>>(states, policies, actions, Wk, Wq, Wv);
  k_noise<<<1024, 256>>>();
  k_final<<<128, 256, 16944 * sizeof(float)>>>(W1, W2, value_out, weight_out);
}

// round 2
// speedup vs baseline: 1.1558x; 1.1558x over previous
#include <cuda_runtime.h>
#include <stdint.h>
#include <math.h>

// B=8, N=16, S=118, A=10, D=128, DK=64, H=2, FO=1
// Restructured:
//   k,q = oa@W^T; av_oa=tanh(oa@Wv^T); av_op=tanh(op@Wv^T)
//   weight = softmax(q.k/8); weighted = (base + w*(dav))/16 + noise_mean
//   value = lrelu(f@W1^T)@W2^T
// noise: partitionable threefry2x32, key (0,42), bits = o0^o1  (verified R1)
// Output: value (2048 f32) then weight (4096 f32).

// ---------------- scratch ----------------
__device__ float g_k[16 * 16 * 64];
__device__ float g_q[16 * 16 * 64];
__device__ float g_aoa[16 * 16 * 64];
__device__ float g_aop[16 * 16 * 64];
__device__ float g_nm[16 * 16 * 16 * 64];  // [(bh*16+i)*16+j]*64+e

// ---------------- threefry2x32, key = (0, 42) ----------------
__device__ __forceinline__ void tf2x32(uint32_t x0, uint32_t x1,
                                       uint32_t& o0, uint32_t& o1) {
  const uint32_t k0 = 0u, k1 = 42u;
  const uint32_t k2 = k0 ^ k1 ^ 0x1BD11BDAu;
  x0 += k0; x1 += k1;
#define TF_RND(r) { x0 += x1; x1 = __funnelshift_l(x1, x1, (r)); x1 ^= x0; }
  TF_RND(13) TF_RND(15) TF_RND(26) TF_RND(6)
  x0 += k1; x1 += k2 + 1u;
  TF_RND(17) TF_RND(29) TF_RND(16) TF_RND(24)
  x0 += k2; x1 += k0 + 2u;
  TF_RND(13) TF_RND(15) TF_RND(26) TF_RND(6)
  x0 += k0; x1 += k1 + 3u;
  TF_RND(17) TF_RND(29) TF_RND(16) TF_RND(24)
  x0 += k1; x1 += k2 + 4u;
  TF_RND(13) TF_RND(15) TF_RND(26) TF_RND(6)
  x0 += k2; x1 += k0 + 5u;
#undef TF_RND
  o0 = x0; o1 = x1;
}

// ============ Kernel A: fused projections (CTAs 0..63) + noise (64..1087) ===
// proj CTA id = (bh<<2)|tensor; tensor: 0=k 1=q 2=av_oa(tanh) 3=av_op(tanh)
__global__ void __launch_bounds__(256) k_pn(
    const float* __restrict__ states, const float* __restrict__ policies,
    const float* __restrict__ actions, const float* __restrict__ Wk,
    const float* __restrict__ Wq, const float* __restrict__ Wv) {
  __shared__ float sm[16 * 129 + 64 * 129];  // src | weights (proj path only)
  const int bx = blockIdx.x;
  const int t = threadIdx.x;

  if (bx >= 64) {
    // ---- noise path: one thread per (bh,i,j,e), reduce 16 k samples ----
    const unsigned tid = (bx - 64) * 256u + t;       // < 262144
    const uint32_t cbase = ((tid >> 6) << 10) | (tid & 63u);
    float s = 0.f;
#pragma unroll
    for (int k = 0; k < 16; k++) {
      uint32_t o0, o1;
      tf2x32(0u, cbase + (uint32_t)(k * 64), o0, o1);
      uint32_t bits = o0 ^ o1;
      s += __uint_as_float((bits >> 9) | 0x3f800000u);  // u + 1
    }
    g_nm[tid] = 0.1f * (s * 0.0625f - 1.5f);  // mean_k (u-0.5)*0.1
    return;
  }

  // ---- projection path ----
  float* src_s = sm;           // 16*129
  float* w_s = sm + 16 * 129;  // 64*129
  const int bh = bx >> 2, tensor = bx & 3;
  const int b = bh >> 1, h = bh & 1;
  const bool use_op = (tensor == 3);

  for (int idx = t; idx < 2048; idx += 256) {
    int n = idx >> 7, d = idx & 127;
    float v;
    if (d < 118) v = states[(b * 16 + n) * 118 + d];
    else v = use_op ? policies[(b * 16 + n) * 10 + d - 118]
                    : actions[(b * 16 + n) * 10 + d - 118];
    src_s[n * 129 + d] = v;
  }
  const float* W = (tensor == 0) ? Wk : (tensor == 1) ? Wq : Wv;
  for (int idx = t; idx < 8192; idx += 256)
    w_s[(idx >> 7) * 129 + (idx & 127)] = W[h * 8192 + idx];
  __syncthreads();

  const int el = t & 31;        // e in {el, el+32}
  const int n0 = (t >> 5) * 2;  // n in {n0, n0+1} (warp-uniform)
  float a00 = 0.f, a01 = 0.f, a10 = 0.f, a11 = 0.f;
#pragma unroll 8
  for (int d = 0; d < 128; d++) {
    float w0 = w_s[el * 129 + d];
    float w1 = w_s[(el + 32) * 129 + d];
    float x0 = src_s[n0 * 129 + d];
    float x1 = src_s[(n0 + 1) * 129 + d];
    a00 = fmaf(x0, w0, a00); a01 = fmaf(x0, w1, a01);
    a10 = fmaf(x1, w0, a10); a11 = fmaf(x1, w1, a11);
  }
  if (tensor >= 2) {
    a00 = tanhf(a00); a01 = tanhf(a01); a10 = tanhf(a10); a11 = tanhf(a11);
  }
  float* outp = (tensor == 0) ? g_k : (tensor == 1) ? g_q
               : (tensor == 2) ? g_aoa : g_aop;
  const int base = bh * 1024;
  outp[base + n0 * 64 + el]            = a00;
  outp[base + n0 * 64 + el + 32]       = a01;
  outp[base + (n0 + 1) * 64 + el]      = a10;
  outp[base + (n0 + 1) * 64 + el + 32] = a11;
}

// ============ Kernel B: softmax + assemble + MLP. grid = 128 = b*16+i ======
// smem (floats): W1s 64*132 | fsh 16*132 | qs 2080 | aoas 2080 | aops 2080
//                ki 128 | W2s 64 | sc 32 | wr 32 | bases 128   = 17184
__global__ void __launch_bounds__(256) k_final(
    const float* __restrict__ W1, const float* __restrict__ W2,
    float* __restrict__ value_out, float* __restrict__ weight_out) {
  extern __shared__ float smd[];
  float* W1s   = smd;             // 64*132 = 8448 (float4-aligned rows, pad 33 u)
  float* fsh   = W1s + 8448;      // 16*132 = 2112
  float* qs    = fsh + 2112;      // 2*16*65 = 2080
  float* aoas  = qs + 2080;
  float* aops  = aoas + 2080;
  float* ki    = aops + 2080;     // 128
  float* W2s   = ki + 128;        // 64
  float* sc    = W2s + 64;        // 32
  float* wr    = sc + 32;         // 32
  float* bases = wr + 32;         // 128
  const int bi = blockIdx.x;
  const int b = bi >> 4, i = bi & 15;
  const int t = threadIdx.x;

  // stage W1 [64][128] -> [64][132] via float4
  {
    const float4* W1v = (const float4*)W1;
    for (int idx = t; idx < 2048; idx += 256) {
      int c = idx >> 5, d4 = idx & 31;
      ((float4*)(W1s + c * 132))[d4] = W1v[idx];
    }
  }
  if (t < 64) W2s[t] = W2[t];
  for (int idx = t; idx < 2048; idx += 256) {
    int h = idx >> 10, rest = idx & 1023;
    int j = rest >> 6, e = rest & 63;
    int g = (b * 2 + h) * 1024 + j * 64 + e;
    int s = h * 1040 + j * 65 + e;
    qs[s]   = g_q[g];
    aoas[s] = g_aoa[g];
    aops[s] = g_aop[g];
  }
  if (t < 128) {
    int h = t >> 6, e = t & 63;
    ki[t] = g_k[(b * 2 + h) * 1024 + i * 64 + e];
  }
  __syncthreads();

  // scores[h][j] = q[h,j] . k[h,i] / 8
  if (t < 32) {
    int h = t >> 4, j = t & 15;
    float acc = 0.f;
#pragma unroll
    for (int e = 0; e < 64; e++)
      acc = fmaf(qs[h * 1040 + j * 65 + e], ki[h * 64 + e], acc);
    sc[h * 16 + j] = acc * 0.125f;
  }
  __syncthreads();

  // softmax rows + emit weight output
  if (t < 2) {
    int h = t;
    float m = -3.4e38f;
#pragma unroll
    for (int j = 0; j < 16; j++) m = fmaxf(m, sc[h * 16 + j]);
    float ex[16]; float ssum = 0.f;
#pragma unroll
    for (int j = 0; j < 16; j++) { ex[j] = expf(sc[h * 16 + j] - m); ssum += ex[j]; }
    float inv = 1.f / ssum;
#pragma unroll
    for (int j = 0; j < 16; j++) {
      float w = ex[j] * inv;
      wr[h * 16 + j] = w;
      if (weight_out) weight_out[((b * 2 + h) * 16 + i) * 16 + j] = w;
    }
  }
  __syncthreads();

  // base[h,e] = (1/16) sum_k w[h,k]*av_oa[h,k,e]
  if (t < 128) {
    int h = t >> 6, e = t & 63;
    float acc = 0.f;
#pragma unroll
    for (int k = 0; k < 16; k++)
      acc = fmaf(wr[h * 16 + k], aoas[h * 1040 + k * 65 + e], acc);
    bases[t] = acc * 0.0625f;
  }
  __syncthreads();

  // f[j][d], d = h*64+e
  for (int idx = t; idx < 2048; idx += 256) {
    int j = idx >> 7, d = idx & 127;
    int h = d >> 6, e = d & 63;
    int s = h * 1040 + j * 65 + e;
    float df = (aops[s] - aoas[s]) * 0.0625f;
    float nm = g_nm[(((b * 2 + h) * 16 + i) * 16 + j) * 64 + e];
    fsh[j * 132 + d] = fmaf(wr[h * 16 + j], df, bases[h * 64 + e]) + nm;
  }
  __syncthreads();

  // v[j,c] = lrelu(f[j].W1[c]); value[j] = sum_c v[j,c]*W2[c]
  // float4 LDS: row stride 132 floats = 33 16B-units -> conflict-free phases
  const int lane = t & 31, jp = t >> 5;
  const int j0 = jp * 2, j1 = j0 + 1;
  const int c0 = lane, c1 = lane + 32;
  const float4* f0p = (const float4*)(fsh + j0 * 132);
  const float4* f1p = (const float4*)(fsh + j1 * 132);
  const float4* w0p = (const float4*)(W1s + c0 * 132);
  const float4* w1p = (const float4*)(W1s + c1 * 132);
  float a00 = 0.f, a01 = 0.f, a10 = 0.f, a11 = 0.f;
#pragma unroll 8
  for (int d4 = 0; d4 < 32; d4++) {
    float4 f0 = f0p[d4], f1 = f1p[d4];
    float4 w0 = w0p[d4], w1 = w1p[d4];
    a00 = fmaf(f0.x, w0.x, a00); a01 = fmaf(f0.x, w1.x, a01);
    a10 = fmaf(f1.x, w0.x, a10); a11 = fmaf(f1.x, w1.x, a11);
    a00 = fmaf(f0.y, w0.y, a00); a01 = fmaf(f0.y, w1.y, a01);
    a10 = fmaf(f1.y, w0.y, a10); a11 = fmaf(f1.y, w1.y, a11);
    a00 = fmaf(f0.z, w0.z, a00); a01 = fmaf(f0.z, w1.z, a01);
    a10 = fmaf(f1.z, w0.z, a10); a11 = fmaf(f1.z, w1.z, a11);
    a00 = fmaf(f0.w, w0.w, a00); a01 = fmaf(f0.w, w1.w, a01);
    a10 = fmaf(f1.w, w0.w, a10); a11 = fmaf(f1.w, w1.w, a11);
  }
  a00 = a00 > 0.f ? a00 : 0.01f * a00;
  a01 = a01 > 0.f ? a01 : 0.01f * a01;
  a10 = a10 > 0.f ? a10 : 0.01f * a10;
  a11 = a11 > 0.f ? a11 : 0.01f * a11;
  float s0 = a00 * W2s[c0] + a01 * W2s[c1];
  float s1 = a10 * W2s[c0] + a11 * W2s[c1];
#pragma unroll
  for (int o = 16; o; o >>= 1) {
    s0 += __shfl_xor_sync(0xffffffffu, s0, o);
    s1 += __shfl_xor_sync(0xffffffffu, s1, o);
  }
  if (lane == 0 && value_out) {
    value_out[bi * 16 + j0] = s0;
    value_out[bi * 16 + j1] = s1;
  }
}

// ---------------- launch ----------------
extern "C" void kernel_launch(void* const* d_in, const int* in_sizes, int n_in,
                              void* d_out, int out_size) {
  const float* states   = (const float*)d_in[0];
  const float* policies = (const float*)d_in[1];
  const float* actions  = (const float*)d_in[2];
  const float* Wk = (const float*)d_in[3];
  const float* Wq = (const float*)d_in[4];
  const float* Wv = (const float*)d_in[5];
  const float* W1 = (const float*)d_in[6];
  const float* W2 = (const float*)d_in[7];

  float* out = (float*)d_out;
  float* value_out = out;
  float* weight_out = nullptr;
  if (out_size >= 6144) {
    weight_out = out + 2048;
  } else if (out_size == 4096) {
    weight_out = out; value_out = nullptr;
  }

  cudaFuncSetAttribute(k_final, cudaFuncAttributeMaxDynamicSharedMemorySize,
                       17184 * (int)sizeof(float));

  k_pn<<<64 + 1024, 256>>>(states, policies, actions, Wk, Wq, Wv);
  k_final<<<128, 256, 17184 * sizeof(float)>>>(W1, W2, value_out, weight_out);
}

// round 3
// speedup vs baseline: 1.4986x; 1.2966x over previous
#include <cuda_runtime.h>
#include <stdint.h>
#include <math.h>

// B=8, N=16, S=118, A=10, D=128, DK=64, H=2, FO=1
// k,q = oa@W^T; av_oa=tanh(oa@Wv^T); av_op=tanh(op@Wv^T)
// weight = softmax(q.k/8); weighted = (base + w*dav)/16 + noise_mean
// value = lrelu(f@W1^T)@W2^T
// noise: partitionable threefry2x32, key (0,42), bits=o0^o1 (verified R1)
// Output: value (2048 f32) then weight (4096 f32).

// ---------------- scratch ----------------
__device__ float g_k[16 * 16 * 64];
__device__ float g_q[16 * 16 * 64];
__device__ float g_aoa[16 * 16 * 64];
__device__ float g_aop[16 * 16 * 64];
__device__ float g_nm[16 * 16 * 16 * 64];  // [(bh*16+i)*16+j]*64+e

// ---------------- threefry2x32, key = (0, 42) ----------------
__device__ __forceinline__ void tf2x32(uint32_t x0, uint32_t x1,
                                       uint32_t& o0, uint32_t& o1) {
  const uint32_t k0 = 0u, k1 = 42u;
  const uint32_t k2 = k0 ^ k1 ^ 0x1BD11BDAu;
  x0 += k0; x1 += k1;
#define TF_RND(r) { x0 += x1; x1 = __funnelshift_l(x1, x1, (r)); x1 ^= x0; }
  TF_RND(13) TF_RND(15) TF_RND(26) TF_RND(6)
  x0 += k1; x1 += k2 + 1u;
  TF_RND(17) TF_RND(29) TF_RND(16) TF_RND(24)
  x0 += k2; x1 += k0 + 2u;
  TF_RND(13) TF_RND(15) TF_RND(26) TF_RND(6)
  x0 += k0; x1 += k1 + 3u;
  TF_RND(17) TF_RND(29) TF_RND(16) TF_RND(24)
  x0 += k1; x1 += k2 + 4u;
  TF_RND(13) TF_RND(15) TF_RND(26) TF_RND(6)
  x0 += k2; x1 += k0 + 5u;
#undef TF_RND
  o0 = x0; o1 = x1;
}

// ============ Kernel A: fused projections (CTAs 0..63) + noise (64..1087) ===
__global__ void __launch_bounds__(256) k_pn(
    const float* __restrict__ states, const float* __restrict__ policies,
    const float* __restrict__ actions, const float* __restrict__ Wk,
    const float* __restrict__ Wq, const float* __restrict__ Wv) {
  __shared__ float sm[16 * 129 + 64 * 129];
  const int bx = blockIdx.x;
  const int t = threadIdx.x;

  if (bx >= 64) {
    const unsigned tid = (bx - 64) * 256u + t;  // < 262144
    const uint32_t cbase = ((tid >> 6) << 10) | (tid & 63u);
    float s = 0.f;
#pragma unroll
    for (int k = 0; k < 16; k++) {
      uint32_t o0, o1;
      tf2x32(0u, cbase + (uint32_t)(k * 64), o0, o1);
      uint32_t bits = o0 ^ o1;
      s += __uint_as_float((bits >> 9) | 0x3f800000u);  // u + 1
    }
    g_nm[tid] = 0.1f * (s * 0.0625f - 1.5f);
    return;
  }

  float* src_s = sm;
  float* w_s = sm + 16 * 129;
  const int bh = bx >> 2, tensor = bx & 3;
  const int b = bh >> 1, h = bh & 1;
  const bool use_op = (tensor == 3);

  for (int idx = t; idx < 2048; idx += 256) {
    int n = idx >> 7, d = idx & 127;
    float v;
    if (d < 118) v = states[(b * 16 + n) * 118 + d];
    else v = use_op ? policies[(b * 16 + n) * 10 + d - 118]
                    : actions[(b * 16 + n) * 10 + d - 118];
    src_s[n * 129 + d] = v;
  }
  const float* W = (tensor == 0) ? Wk : (tensor == 1) ? Wq : Wv;
  for (int idx = t; idx < 8192; idx += 256)
    w_s[(idx >> 7) * 129 + (idx & 127)] = W[h * 8192 + idx];
  __syncthreads();

  const int el = t & 31;
  const int n0 = (t >> 5) * 2;
  float a00 = 0.f, a01 = 0.f, a10 = 0.f, a11 = 0.f;
#pragma unroll 8
  for (int d = 0; d < 128; d++) {
    float w0 = w_s[el * 129 + d];
    float w1 = w_s[(el + 32) * 129 + d];
    float x0 = src_s[n0 * 129 + d];
    float x1 = src_s[(n0 + 1) * 129 + d];
    a00 = fmaf(x0, w0, a00); a01 = fmaf(x0, w1, a01);
    a10 = fmaf(x1, w0, a10); a11 = fmaf(x1, w1, a11);
  }
  if (tensor >= 2) {
    a00 = tanhf(a00); a01 = tanhf(a01); a10 = tanhf(a10); a11 = tanhf(a11);
  }
  float* outp = (tensor == 0) ? g_k : (tensor == 1) ? g_q
               : (tensor == 2) ? g_aoa : g_aop;
  const int base = bh * 1024;
  outp[base + n0 * 64 + el]            = a00;
  outp[base + n0 * 64 + el + 32]       = a01;
  outp[base + (n0 + 1) * 64 + el]      = a10;
  outp[base + (n0 + 1) * 64 + el + 32] = a11;
}

// ============ Kernel B: per-(b,i), 512 threads, latency-optimized ==========
__global__ void __launch_bounds__(512) k_final(
    const float* __restrict__ W1, const float* __restrict__ W2,
    float* __restrict__ value_out, float* __restrict__ weight_out) {
  extern __shared__ float smd[];
  float* W1s   = smd;             // 64*132 = 8448
  float* fsh   = W1s + 8448;      // 16*132 = 2112
  float* qs    = fsh + 2112;      // 2*16*65 = 2080
  float* aoas  = qs + 2080;
  float* aops  = aoas + 2080;
  float* ki    = aops + 2080;     // 128
  float* W2s   = ki + 128;        // 64
  float* sc    = W2s + 64;        // 32
  float* wr    = sc + 32;         // 32
  float* bases = wr + 32;         // 128
  const int bi = blockIdx.x;
  const int b = bi >> 4, i = bi & 15;
  const int t = threadIdx.x;
  const int lane = t & 31, warp = t >> 5;

  // --- prefetch noise means for the f-phase into registers (hides latency) ---
  float rnm[4];
#pragma unroll
  for (int r = 0; r < 4; r++) {
    int idx = t + r * 512;            // -> (j = idx>>7, d = idx&127)
    int j = idx >> 7, d = idx & 127;
    int h = d >> 6, e = d & 63;
    rnm[r] = g_nm[(((b * 2 + h) * 16 + i) * 16 + j) * 64 + e];
  }

  // --- stage weights + activations to smem ---
  {
    const float4* W1v = (const float4*)W1;
#pragma unroll
    for (int r = 0; r < 4; r++) {
      int idx = t + r * 512;          // 2048 float4
      int c = idx >> 5, d4 = idx & 31;
      ((float4*)(W1s + c * 132))[d4] = W1v[idx];
    }
  }
  if (t < 64) W2s[t] = W2[t];
#pragma unroll
  for (int r = 0; r < 4; r++) {
    int idx = t + r * 512;
    int h = idx >> 10, rest = idx & 1023;
    int j = rest >> 6, e = rest & 63;
    int g = (b * 2 + h) * 1024 + j * 64 + e;
    int s = h * 1040 + j * 65 + e;
    qs[s]   = g_q[g];
    aoas[s] = g_aoa[g];
    aops[s] = g_aop[g];
  }
  if (t < 128) {
    int h = t >> 6, e = t & 63;
    ki[t] = g_k[(b * 2 + h) * 1024 + i * 64 + e];
  }
  __syncthreads();

  // --- scores: warp w handles pairs p=2w, 2w+1; lanes split e; shfl reduce ---
  {
    const int p0 = warp * 2;
    float acc0 = 0.f, acc1 = 0.f;
    {
      int h = p0 >> 4, j = p0 & 15;
      acc0 = qs[h * 1040 + j * 65 + lane]      * ki[h * 64 + lane]
           + qs[h * 1040 + j * 65 + lane + 32] * ki[h * 64 + lane + 32];
    }
    {
      int p1 = p0 + 1;
      int h = p1 >> 4, j = p1 & 15;
      acc1 = qs[h * 1040 + j * 65 + lane]      * ki[h * 64 + lane]
           + qs[h * 1040 + j * 65 + lane + 32] * ki[h * 64 + lane + 32];
    }
#pragma unroll
    for (int o = 16; o; o >>= 1) {
      acc0 += __shfl_xor_sync(0xffffffffu, acc0, o);
      acc1 += __shfl_xor_sync(0xffffffffu, acc1, o);
    }
    if (lane == 0) { sc[p0] = acc0 * 0.125f; sc[p0 + 1] = acc1 * 0.125f; }
  }
  __syncthreads();

  // --- softmax: 32 threads, width-16 shuffles ---
  if (t < 32) {
    float x = sc[t];
    float m = x;
#pragma unroll
    for (int o = 8; o; o >>= 1)
      m = fmaxf(m, __shfl_xor_sync(0xffffffffu, m, o, 16));
    float ex = expf(x - m);
    float ssum = ex;
#pragma unroll
    for (int o = 8; o; o >>= 1)
      ssum += __shfl_xor_sync(0xffffffffu, ssum, o, 16);
    float w = ex / ssum;
    wr[t] = w;
    if (weight_out) {
      int h = t >> 4, j = t & 15;
      weight_out[((b * 2 + h) * 16 + i) * 16 + j] = w;
    }
  }
  __syncthreads();

  // --- base[h,e] = (1/16) sum_k w[h,k]*av_oa[h,k,e] ---
  if (t < 128) {
    int h = t >> 6, e = t & 63;
    float acc = 0.f;
#pragma unroll
    for (int k = 0; k < 16; k++)
      acc = fmaf(wr[h * 16 + k], aoas[h * 1040 + k * 65 + e], acc);
    bases[t] = acc * 0.0625f;
  }
  __syncthreads();

  // --- f[j][d] assemble (uses prefetched rnm) ---
#pragma unroll
  for (int r = 0; r < 4; r++) {
    int idx = t + r * 512;
    int j = idx >> 7, d = idx & 127;
    int h = d >> 6, e = d & 63;
    int s = h * 1040 + j * 65 + e;
    float df = (aops[s] - aoas[s]) * 0.0625f;
    fsh[j * 132 + d] = fmaf(wr[h * 16 + j], df, bases[h * 64 + e]) + rnm[r];
  }
  __syncthreads();

  // --- MLP: 256 threads, 2x2 tiles, float4 LDS (warp-uniform j -> bcast) ---
  if (t < 256) {
    const int jp = t >> 5;            // warp-uniform
    const int j0 = jp * 2, j1 = j0 + 1;
    const int c0 = lane, c1 = lane + 32;
    const float4* f0p = (const float4*)(fsh + j0 * 132);
    const float4* f1p = (const float4*)(fsh + j1 * 132);
    const float4* w0p = (const float4*)(W1s + c0 * 132);
    const float4* w1p = (const float4*)(W1s + c1 * 132);
    float a00 = 0.f, a01 = 0.f, a10 = 0.f, a11 = 0.f;
#pragma unroll 8
    for (int d4 = 0; d4 < 32; d4++) {
      float4 f0 = f0p[d4], f1 = f1p[d4];
      float4 w0 = w0p[d4], w1 = w1p[d4];
      a00 = fmaf(f0.x, w0.x, a00); a01 = fmaf(f0.x, w1.x, a01);
      a10 = fmaf(f1.x, w0.x, a10); a11 = fmaf(f1.x, w1.x, a11);
      a00 = fmaf(f0.y, w0.y, a00); a01 = fmaf(f0.y, w1.y, a01);
      a10 = fmaf(f1.y, w0.y, a10); a11 = fmaf(f1.y, w1.y, a11);
      a00 = fmaf(f0.z, w0.z, a00); a01 = fmaf(f0.z, w1.z, a01);
      a10 = fmaf(f1.z, w0.z, a10); a11 = fmaf(f1.z, w1.z, a11);
      a00 = fmaf(f0.w, w0.w, a00); a01 = fmaf(f0.w, w1.w, a01);
      a10 = fmaf(f1.w, w0.w, a10); a11 = fmaf(f1.w, w1.w, a11);
    }
    a00 = a00 > 0.f ? a00 : 0.01f * a00;
    a01 = a01 > 0.f ? a01 : 0.01f * a01;
    a10 = a10 > 0.f ? a10 : 0.01f * a10;
    a11 = a11 > 0.f ? a11 : 0.01f * a11;
    float s0 = a00 * W2s[c0] + a01 * W2s[c1];
    float s1 = a10 * W2s[c0] + a11 * W2s[c1];
#pragma unroll
    for (int o = 16; o; o >>= 1) {
      s0 += __shfl_xor_sync(0xffffffffu, s0, o);
      s1 += __shfl_xor_sync(0xffffffffu, s1, o);
    }
    if (lane == 0 && value_out) {
      value_out[bi * 16 + j0] = s0;
      value_out[bi * 16 + j1] = s1;
    }
  }
}

// ---------------- launch ----------------
extern "C" void kernel_launch(void* const* d_in, const int* in_sizes, int n_in,
                              void* d_out, int out_size) {
  const float* states   = (const float*)d_in[0];
  const float* policies = (const float*)d_in[1];
  const float* actions  = (const float*)d_in[2];
  const float* Wk = (const float*)d_in[3];
  const float* Wq = (const float*)d_in[4];
  const float* Wv = (const float*)d_in[5];
  const float* W1 = (const float*)d_in[6];
  const float* W2 = (const float*)d_in[7];

  float* out = (float*)d_out;
  float* value_out = out;
  float* weight_out = nullptr;
  if (out_size >= 6144) {
    weight_out = out + 2048;
  } else if (out_size == 4096) {
    weight_out = out; value_out = nullptr;
  }

  cudaFuncSetAttribute(k_final, cudaFuncAttributeMaxDynamicSharedMemorySize,
                       17184 * (int)sizeof(float));

  k_pn<<<64 + 1024, 256>>>(states, policies, actions, Wk, Wq, Wv);
  k_final<<<128, 512, 17184 * sizeof(float)>>>(W1, W2, value_out, weight_out);
}